// round 3
// baseline (speedup 1.0000x reference)
#include <cuda_runtime.h>
#include <cuda_bf16.h>

// Table-batched embedding bag, SUM pooling.
// inputs (metadata order):
//   d_in[0] indices          int32 or int64  [T*B*L]
//   d_in[1] offsets          int32 or int64  [T*B + 1]   (CSR bag offsets)
//   d_in[2] weights          fp32            [T*E, D]    (stacked tables)
//   d_in[3] hash_size_cumsum int32 or int64  [T + 1]
// output: fp32 [B, T*D]   (bag g = t*B + b  ->  out[b, t*D : (t+1)*D])
//
// JAX without x64 silently downcasts int64 -> int32; we detect the integer
// width at runtime from offsets (strictly increasing from 0):
//   ((const int*)offsets)[1] == 0  <=>  data is int64 (high word of offsets[0])
//   otherwise                       =>  data is int32 (offsets[1] = L > 0)
//
// Strategy: one warp per bag. 32 lanes x float4 = one D=128 row per
// warp-load (4x 128B coalesced lines). MLP=4 via 4 independent
// accumulators over the L=20 indices. Pure DRAM-bound gather.

__device__ __forceinline__ float4 f4add(float4 a, float4 b) {
    a.x += b.x; a.y += b.y; a.z += b.z; a.w += b.w;
    return a;
}

template <typename IdxT>
__device__ __forceinline__
void tbe_bag_d128(const IdxT* __restrict__ indices,
                  const IdxT* __restrict__ offsets,
                  const float* __restrict__ weights,
                  const IdxT* __restrict__ hash_cumsum,
                  float* __restrict__ out,
                  int bag, int batch, int n_tables, int lane) {
    const int table = bag / batch;          // feature-major bag layout
    const int b     = bag - table * batch;

    const int start = (int)offsets[bag];
    const int end   = (int)offsets[bag + 1];
    const int base  = (int)hash_cumsum[table];  // < 4M rows, fits int32

    const float4* __restrict__ w4 = (const float4*)weights;

    float4 a0 = make_float4(0.f, 0.f, 0.f, 0.f);
    float4 a1 = a0, a2 = a0, a3 = a0;

    int j = start;
    for (; j + 4 <= end; j += 4) {
        const int r0 = (int)__ldg(&indices[j + 0]) + base;
        const int r1 = (int)__ldg(&indices[j + 1]) + base;
        const int r2 = (int)__ldg(&indices[j + 2]) + base;
        const int r3 = (int)__ldg(&indices[j + 3]) + base;
        float4 v0 = w4[(long long)r0 * 32 + lane];
        float4 v1 = w4[(long long)r1 * 32 + lane];
        float4 v2 = w4[(long long)r2 * 32 + lane];
        float4 v3 = w4[(long long)r3 * 32 + lane];
        a0 = f4add(a0, v0);
        a1 = f4add(a1, v1);
        a2 = f4add(a2, v2);
        a3 = f4add(a3, v3);
    }
    for (; j < end; ++j) {
        const int r = (int)__ldg(&indices[j]) + base;
        a0 = f4add(a0, w4[(long long)r * 32 + lane]);
    }

    float4 acc = f4add(f4add(a0, a1), f4add(a2, a3));

    float4* __restrict__ o4 = (float4*)out;
    o4[((long long)b * n_tables + table) * 32 + lane] = acc;
}

__global__ __launch_bounds__(256)
void tbe_fwd_d128_kernel(const void* __restrict__ indices_raw,
                         const void* __restrict__ offsets_raw,
                         const float* __restrict__ weights,
                         const void* __restrict__ hash_cumsum_raw,
                         float* __restrict__ out,
                         int num_bags, int batch, int n_tables) {
    const int warp_id = (blockIdx.x * blockDim.x + threadIdx.x) >> 5;
    const int lane    = threadIdx.x & 31;
    if (warp_id >= num_bags) return;

    // dtype sniff: offsets strictly increasing from 0 (uniform branch)
    const bool is64 = (((const int*)offsets_raw)[1] == 0);

    if (is64) {
        tbe_bag_d128<long long>((const long long*)indices_raw,
                                (const long long*)offsets_raw,
                                weights,
                                (const long long*)hash_cumsum_raw,
                                out, warp_id, batch, n_tables, lane);
    } else {
        tbe_bag_d128<int>((const int*)indices_raw,
                          (const int*)offsets_raw,
                          weights,
                          (const int*)hash_cumsum_raw,
                          out, warp_id, batch, n_tables, lane);
    }
}

// Generic fallback for D != 128: one thread per output element.
template <typename IdxT>
__global__ void tbe_fwd_generic_kernel(const IdxT* __restrict__ indices,
                                       const IdxT* __restrict__ offsets,
                                       const float* __restrict__ weights,
                                       const IdxT* __restrict__ hash_cumsum,
                                       float* __restrict__ out,
                                       int num_bags, int batch, int n_tables,
                                       int D) {
    long long gid = (long long)blockIdx.x * blockDim.x + threadIdx.x;
    long long total = (long long)num_bags * D;
    if (gid >= total) return;
    int bag = (int)(gid / D);
    int d   = (int)(gid - (long long)bag * D);
    int table = bag / batch;
    int b     = bag - table * batch;
    long long start = (long long)offsets[bag];
    long long end   = (long long)offsets[bag + 1];
    long long base  = (long long)hash_cumsum[table];
    float acc = 0.f;
    for (long long j = start; j < end; ++j) {
        long long row = (long long)indices[j] + base;
        acc += weights[row * D + d];
    }
    out[((long long)b * n_tables + table) * D + d] = acc;
}

extern "C" void kernel_launch(void* const* d_in, const int* in_sizes, int n_in,
                              void* d_out, int out_size) {
    const void*  indices     = d_in[0];
    const void*  offsets     = d_in[1];
    const float* weights     = (const float*)d_in[2];
    const void*  hash_cumsum = d_in[3];
    float* out = (float*)d_out;

    const int num_bags = in_sizes[1] - 1;        // T*B
    const int n_tables = in_sizes[3] - 1;        // T
    const int batch    = num_bags / n_tables;    // B
    const int D        = out_size / num_bags;    // 128 expected

    if (D == 128) {
        const int warps_per_block = 8;
        const int grid = (num_bags + warps_per_block - 1) / warps_per_block;
        tbe_fwd_d128_kernel<<<grid, 256>>>(indices, offsets, weights,
                                           hash_cumsum, out,
                                           num_bags, batch, n_tables);
    } else {
        long long total = (long long)num_bags * D;
        int grid = (int)((total + 255) / 256);
        tbe_fwd_generic_kernel<int><<<grid, 256>>>(
            (const int*)indices, (const int*)offsets, weights,
            (const int*)hash_cumsum, out, num_bags, batch, n_tables, D);
    }
}

// round 5
// speedup vs baseline: 1.0306x; 1.0306x over previous
#include <cuda_runtime.h>
#include <cuda_bf16.h>
#include <cstdint>

// Table-batched embedding bag, SUM pooling.
// inputs (metadata order):
//   d_in[0] indices          int32 or int64  [T*B*L]
//   d_in[1] offsets          int32 or int64  [T*B + 1]   (CSR bag offsets)
//   d_in[2] weights          fp32            [T*E, D]    (stacked tables)
//   d_in[3] hash_size_cumsum int32 or int64  [T + 1]
// output: fp32 [B, T*D]   (bag g = t*B + b  ->  out[b, t*D : (t+1)*D])
//
// dtype sniff (JAX downcasts int64->int32 by default): offsets strictly
// increase from 0, so ((const int*)offsets)[1]==0 <=> int64 data.
//
// R4 strategy: one warp per bag; rows fetched via cp.async.cg (16B/lane,
// L2-only, zero dest registers) into a per-warp 8-slot x 512B smem ring,
// 4 rows in flight. Indices preloaded one-per-lane + shfl distribution.
// Decouples MLP from register pressure -> higher occupancy + deeper queues.

#define FULL_MASK 0xFFFFFFFFu

__device__ __forceinline__ void cp_async16(uint32_t smem_addr, const void* gptr) {
    asm volatile("cp.async.cg.shared.global [%0], [%1], 16;\n"
                 :: "r"(smem_addr), "l"(gptr));
}
__device__ __forceinline__ void cp_commit() {
    asm volatile("cp.async.commit_group;\n" ::: "memory");
}
template <int N>
__device__ __forceinline__ void cp_wait() {
    asm volatile("cp.async.wait_group %0;\n" :: "n"(N) : "memory");
}

// ring: [8 warps][8 slots][32 lanes] float4 = 32 KB per 256-thread block
#define SLOTS 8
#define AHEAD 4   // rows in flight per warp

template <typename IdxT>
__device__ __forceinline__
void bag_pipe(const IdxT* __restrict__ indices,
              const IdxT* __restrict__ offsets,
              const float* __restrict__ weights,
              const IdxT* __restrict__ hash_cumsum,
              float* __restrict__ out,
              uint32_t smem_warp_base,       // byte addr of this warp's ring
              const float4* __restrict__ ring_warp,  // generic ptr, same region
              int bag, int batch, int n_tables, int lane) {
    const int table = bag / batch;          // feature-major bag layout
    const int b     = bag - table * batch;

    const int start = (int)offsets[bag];
    const int count = (int)offsets[bag + 1] - start;
    const int base  = (int)hash_cumsum[table];   // < 4M rows, fits int32

    const float4* __restrict__ w4 = (const float4*)weights;

    // Preload up to 32 bag indices, one per lane (single coalesced load).
    int myidx = 0;
    if (lane < count) myidx = (int)indices[start + lane];

    // Prologue: issue first AHEAD rows (empty commit groups keep counting).
    #pragma unroll
    for (int p = 0; p < AHEAD; ++p) {
        if (p < count) {
            const int r = __shfl_sync(FULL_MASK, myidx, p) + base;
            cp_async16(smem_warp_base + (uint32_t)(((p & (SLOTS - 1)) * 32 + lane) << 4),
                       (const void*)&w4[(long long)r * 32 + lane]);
        }
        cp_commit();
    }

    float4 acc = make_float4(0.f, 0.f, 0.f, 0.f);
    for (int j = 0; j < count; ++j) {
        cp_wait<AHEAD - 1>();   // group j complete -> slot j&7 ready
        const float4 v = ring_warp[(j & (SLOTS - 1)) * 32 + lane];
        const int nj = j + AHEAD;
        if (nj < count) {
            int r;
            if (nj < 32) r = __shfl_sync(FULL_MASK, myidx, nj) + base;
            else         r = (int)indices[start + nj] + base;
            cp_async16(smem_warp_base + (uint32_t)(((nj & (SLOTS - 1)) * 32 + lane) << 4),
                       (const void*)&w4[(long long)r * 32 + lane]);
        }
        cp_commit();
        acc.x += v.x; acc.y += v.y; acc.z += v.z; acc.w += v.w;
    }
    cp_wait<0>();   // drain trailing empty groups

    ((float4*)out)[((long long)b * n_tables + table) * 32 + lane] = acc;
}

__global__ __launch_bounds__(256)
void tbe_fwd_d128_kernel(const void* __restrict__ indices_raw,
                         const void* __restrict__ offsets_raw,
                         const float* __restrict__ weights,
                         const void* __restrict__ hash_cumsum_raw,
                         float* __restrict__ out,
                         int num_bags, int batch, int n_tables) {
    __shared__ __align__(16) float4 ring[8 * SLOTS * 32];   // 32 KB

    const int warp = threadIdx.x >> 5;
    const int lane = threadIdx.x & 31;
    const int bag  = blockIdx.x * 8 + warp;
    if (bag >= num_bags) return;

    float4* ring_warp = &ring[warp * SLOTS * 32];
    const uint32_t smem_warp_base =
        (uint32_t)__cvta_generic_to_shared(ring_warp);

    // dtype sniff: offsets strictly increasing from 0 (uniform branch)
    const bool is64 = (((const int*)offsets_raw)[1] == 0);

    if (is64) {
        bag_pipe<long long>((const long long*)indices_raw,
                            (const long long*)offsets_raw,
                            weights,
                            (const long long*)hash_cumsum_raw,
                            out, smem_warp_base, ring_warp,
                            bag, batch, n_tables, lane);
    } else {
        bag_pipe<int>((const int*)indices_raw,
                      (const int*)offsets_raw,
                      weights,
                      (const int*)hash_cumsum_raw,
                      out, smem_warp_base, ring_warp,
                      bag, batch, n_tables, lane);
    }
}

// Generic fallback for D != 128: one thread per output element (int32 idx).
template <typename IdxT>
__global__ void tbe_fwd_generic_kernel(const IdxT* __restrict__ indices,
                                       const IdxT* __restrict__ offsets,
                                       const float* __restrict__ weights,
                                       const IdxT* __restrict__ hash_cumsum,
                                       float* __restrict__ out,
                                       int num_bags, int batch, int n_tables,
                                       int D) {
    long long gid = (long long)blockIdx.x * blockDim.x + threadIdx.x;
    long long total = (long long)num_bags * D;
    if (gid >= total) return;
    int bag = (int)(gid / D);
    int d   = (int)(gid - (long long)bag * D);
    int table = bag / batch;
    int b     = bag - table * batch;
    long long start = (long long)offsets[bag];
    long long end   = (long long)offsets[bag + 1];
    long long base  = (long long)hash_cumsum[table];
    float acc = 0.f;
    for (long long j = start; j < end; ++j) {
        long long row = (long long)indices[j] + base;
        acc += weights[row * D + d];
    }
    out[((long long)b * n_tables + table) * D + d] = acc;
}

extern "C" void kernel_launch(void* const* d_in, const int* in_sizes, int n_in,
                              void* d_out, int out_size) {
    const void*  indices     = d_in[0];
    const void*  offsets     = d_in[1];
    const float* weights     = (const float*)d_in[2];
    const void*  hash_cumsum = d_in[3];
    float* out = (float*)d_out;

    const int num_bags = in_sizes[1] - 1;        // T*B
    const int n_tables = in_sizes[3] - 1;        // T
    const int batch    = num_bags / n_tables;    // B
    const int D        = out_size / num_bags;    // 128 expected

    if (D == 128) {
        const int warps_per_block = 8;
        const int grid = (num_bags + warps_per_block - 1) / warps_per_block;
        tbe_fwd_d128_kernel<<<grid, 256>>>(indices, offsets, weights,
                                           hash_cumsum, out,
                                           num_bags, batch, n_tables);
    } else {
        long long total = (long long)num_bags * D;
        int grid = (int)((total + 255) / 256);
        tbe_fwd_generic_kernel<int><<<grid, 256>>>(
            (const int*)indices, (const int*)offsets, weights,
            (const int*)hash_cumsum, out, num_bags, batch, n_tables, D);
    }
}

// round 7
// speedup vs baseline: 1.0402x; 1.0094x over previous
#include <cuda_runtime.h>
#include <cuda_bf16.h>
#include <cstdint>

// Table-batched embedding bag, SUM pooling.
// inputs (metadata order):
//   d_in[0] indices          int32 or int64  [T*B*L]
//   d_in[1] offsets          int32 or int64  [T*B + 1]   (CSR bag offsets)
//   d_in[2] weights          fp32            [T*E, D]    (stacked tables)
//   d_in[3] hash_size_cumsum int32 or int64  [T + 1]
// output: fp32 [B, T*D]   (bag g = t*B + b  ->  out[b, t*D : (t+1)*D])
//
// dtype sniff (JAX downcasts int64->int32 by default): offsets strictly
// increase from 0, so ((const int*)offsets)[1]==0 <=> int64 data.
//
// R5 (resubmitted after broker infra failure): cp.async row pipeline,
//   - __launch_bounds__(256, 7): regs <= 36 -> 7 blocks/SM (56 warps)
//   - AHEAD 6 rows in flight per warp
// In-flight bytes/SM ~2x vs R4 (84KB -> ~168KB) to push DRAM% past 70.

#define FULL_MASK 0xFFFFFFFFu

__device__ __forceinline__ void cp_async16(uint32_t smem_addr, const void* gptr) {
    asm volatile("cp.async.cg.shared.global [%0], [%1], 16;\n"
                 :: "r"(smem_addr), "l"(gptr));
}
__device__ __forceinline__ void cp_commit() {
    asm volatile("cp.async.commit_group;\n" ::: "memory");
}
template <int N>
__device__ __forceinline__ void cp_wait() {
    asm volatile("cp.async.wait_group %0;\n" :: "n"(N) : "memory");
}

// ring: [8 warps][8 slots][32 lanes] float4 = 32 KB per 256-thread block
#define SLOTS 8
#define AHEAD 6   // rows in flight per warp (AHEAD < SLOTS)

template <typename IdxT>
__device__ __forceinline__
void bag_pipe(const IdxT* __restrict__ indices,
              const IdxT* __restrict__ offsets,
              const float* __restrict__ weights,
              const IdxT* __restrict__ hash_cumsum,
              float* __restrict__ out,
              uint32_t smem_warp_base,                 // byte addr of warp ring
              const float4* __restrict__ ring_warp,    // generic ptr, same region
              int bag, int batch, int n_tables, int lane) {
    const int table = bag / batch;          // feature-major bag layout
    const int b     = bag - table * batch;

    const int start = (int)offsets[bag];
    const int count = (int)offsets[bag + 1] - start;
    const int base  = (int)hash_cumsum[table];   // < 4M rows, fits int32

    const float4* __restrict__ w4 = (const float4*)weights;

    // Preload up to 32 bag indices, one per lane (single coalesced load).
    int myidx = 0;
    if (lane < count) myidx = (int)indices[start + lane];

    // Prologue: issue first AHEAD rows (empty commit groups keep counting).
    #pragma unroll
    for (int p = 0; p < AHEAD; ++p) {
        if (p < count) {
            const int r = __shfl_sync(FULL_MASK, myidx, p) + base;
            cp_async16(smem_warp_base + (uint32_t)(((p & (SLOTS - 1)) * 32 + lane) << 4),
                       (const void*)&w4[(long long)r * 32 + lane]);
        }
        cp_commit();
    }

    float4 acc = make_float4(0.f, 0.f, 0.f, 0.f);
    for (int j = 0; j < count; ++j) {
        cp_wait<AHEAD - 1>();   // group j complete -> slot j&7 ready
        const float4 v = ring_warp[(j & (SLOTS - 1)) * 32 + lane];
        const int nj = j + AHEAD;
        if (nj < count) {
            int r;
            if (nj < 32) r = __shfl_sync(FULL_MASK, myidx, nj) + base;
            else         r = (int)indices[start + nj] + base;
            cp_async16(smem_warp_base + (uint32_t)(((nj & (SLOTS - 1)) * 32 + lane) << 4),
                       (const void*)&w4[(long long)r * 32 + lane]);
        }
        cp_commit();
        acc.x += v.x; acc.y += v.y; acc.z += v.z; acc.w += v.w;
    }
    cp_wait<0>();   // drain trailing empty groups

    ((float4*)out)[((long long)b * n_tables + table) * 32 + lane] = acc;
}

__global__ __launch_bounds__(256, 7)
void tbe_fwd_d128_kernel(const void* __restrict__ indices_raw,
                         const void* __restrict__ offsets_raw,
                         const float* __restrict__ weights,
                         const void* __restrict__ hash_cumsum_raw,
                         float* __restrict__ out,
                         int num_bags, int batch, int n_tables) {
    __shared__ __align__(16) float4 ring[8 * SLOTS * 32];   // 32 KB

    const int warp = threadIdx.x >> 5;
    const int lane = threadIdx.x & 31;
    const int bag  = blockIdx.x * 8 + warp;
    if (bag >= num_bags) return;

    float4* ring_warp = &ring[warp * SLOTS * 32];
    const uint32_t smem_warp_base =
        (uint32_t)__cvta_generic_to_shared(ring_warp);

    // dtype sniff: offsets strictly increasing from 0 (uniform branch)
    const bool is64 = (((const int*)offsets_raw)[1] == 0);

    if (is64) {
        bag_pipe<long long>((const long long*)indices_raw,
                            (const long long*)offsets_raw,
                            weights,
                            (const long long*)hash_cumsum_raw,
                            out, smem_warp_base, ring_warp,
                            bag, batch, n_tables, lane);
    } else {
        bag_pipe<int>((const int*)indices_raw,
                      (const int*)offsets_raw,
                      weights,
                      (const int*)hash_cumsum_raw,
                      out, smem_warp_base, ring_warp,
                      bag, batch, n_tables, lane);
    }
}

// Generic fallback for D != 128: one thread per output element (int32 idx).
template <typename IdxT>
__global__ void tbe_fwd_generic_kernel(const IdxT* __restrict__ indices,
                                       const IdxT* __restrict__ offsets,
                                       const float* __restrict__ weights,
                                       const IdxT* __restrict__ hash_cumsum,
                                       float* __restrict__ out,
                                       int num_bags, int batch, int n_tables,
                                       int D) {
    long long gid = (long long)blockIdx.x * blockDim.x + threadIdx.x;
    long long total = (long long)num_bags * D;
    if (gid >= total) return;
    int bag = (int)(gid / D);
    int d   = (int)(gid - (long long)bag * D);
    int table = bag / batch;
    int b     = bag - table * batch;
    long long start = (long long)offsets[bag];
    long long end   = (long long)offsets[bag + 1];
    long long base  = (long long)hash_cumsum[table];
    float acc = 0.f;
    for (long long j = start; j < end; ++j) {
        long long row = (long long)indices[j] + base;
        acc += weights[row * D + d];
    }
    out[((long long)b * n_tables + table) * D + d] = acc;
}

extern "C" void kernel_launch(void* const* d_in, const int* in_sizes, int n_in,
                              void* d_out, int out_size) {
    const void*  indices     = d_in[0];
    const void*  offsets     = d_in[1];
    const float* weights     = (const float*)d_in[2];
    const void*  hash_cumsum = d_in[3];
    float* out = (float*)d_out;

    const int num_bags = in_sizes[1] - 1;        // T*B
    const int n_tables = in_sizes[3] - 1;        // T
    const int batch    = num_bags / n_tables;    // B
    const int D        = out_size / num_bags;    // 128 expected

    if (D == 128) {
        const int warps_per_block = 8;
        const int grid = (num_bags + warps_per_block - 1) / warps_per_block;
        tbe_fwd_d128_kernel<<<grid, 256>>>(indices, offsets, weights,
                                           hash_cumsum, out,
                                           num_bags, batch, n_tables);
    } else {
        long long total = (long long)num_bags * D;
        int grid = (int)((total + 255) / 256);
        tbe_fwd_generic_kernel<int><<<grid, 256>>>(
            (const int*)indices, (const int*)offsets, weights,
            (const int*)hash_cumsum, out, num_bags, batch, n_tables, D);
    }
}

// round 8
// speedup vs baseline: 1.0448x; 1.0044x over previous
#include <cuda_runtime.h>
#include <cuda_bf16.h>
#include <cstdint>

// Table-batched embedding bag, SUM pooling.
// inputs (metadata order):
//   d_in[0] indices          int32 or int64  [T*B*L]
//   d_in[1] offsets          int32 or int64  [T*B + 1]   (CSR bag offsets)
//   d_in[2] weights          fp32            [T*E, D]    (stacked tables)
//   d_in[3] hash_size_cumsum int32 or int64  [T + 1]
// output: fp32 [B, T*D]   (bag g = t*B + b  ->  out[b, t*D : (t+1)*D])
//
// dtype sniff (JAX downcasts int64->int32 by default): offsets strictly
// increase from 0, so ((const int*)offsets)[1]==0 <=> int64 data.
//
// R8: cp.async row pipeline; ring shrunk 8->6 slots (32KB->24KB smem) so
// shared memory no longer caps occupancy. __launch_bounds__(256,8) ->
// 8 blocks/SM = 64 warps (100% theoretical). AHEAD=5 rows in flight/warp.
// In-flight/SM = 64*5*512B = 160KB.

#define FULL_MASK 0xFFFFFFFFu

__device__ __forceinline__ void cp_async16(uint32_t smem_addr, const void* gptr) {
    asm volatile("cp.async.cg.shared.global [%0], [%1], 16;\n"
                 :: "r"(smem_addr), "l"(gptr));
}
__device__ __forceinline__ void cp_commit() {
    asm volatile("cp.async.commit_group;\n" ::: "memory");
}
template <int N>
__device__ __forceinline__ void cp_wait() {
    asm volatile("cp.async.wait_group %0;\n" :: "n"(N) : "memory");
}

// ring: [8 warps][6 slots][32 lanes] float4 = 24 KB per 256-thread block
#define SLOTS 6
#define AHEAD 5   // rows in flight per warp (AHEAD < SLOTS)

template <typename IdxT>
__device__ __forceinline__
void bag_pipe(const IdxT* __restrict__ indices,
              const IdxT* __restrict__ offsets,
              const float* __restrict__ weights,
              const IdxT* __restrict__ hash_cumsum,
              float* __restrict__ out,
              uint32_t smem_warp_base,                 // byte addr of warp ring
              const float4* __restrict__ ring_warp,    // generic ptr, same region
              int bag, int batch, int n_tables, int lane) {
    const int table = bag / batch;          // feature-major bag layout
    const int b     = bag - table * batch;

    const int start = (int)offsets[bag];
    const int count = (int)offsets[bag + 1] - start;
    const int base  = (int)hash_cumsum[table];   // < 4M rows, fits int32

    const float4* __restrict__ w4 = (const float4*)weights;

    // Preload up to 32 bag indices, one per lane (single coalesced load).
    int myidx = 0;
    if (lane < count) myidx = (int)indices[start + lane];

    // Prologue: issue first AHEAD rows into slots 0..AHEAD-1.
    #pragma unroll
    for (int p = 0; p < AHEAD; ++p) {
        if (p < count) {
            const int r = __shfl_sync(FULL_MASK, myidx, p) + base;
            cp_async16(smem_warp_base + (uint32_t)((p * 32 + lane) << 4),
                       (const void*)&w4[(long long)r * 32 + lane]);
        }
        cp_commit();
    }

    // Ring counters (SLOTS is not a power of two).
    int rs = 0;                 // read slot for iteration j
    int ws = AHEAD;             // write slot for row j+AHEAD  (AHEAD < SLOTS)

    float4 acc = make_float4(0.f, 0.f, 0.f, 0.f);
    for (int j = 0; j < count; ++j) {
        cp_wait<AHEAD - 1>();   // group j complete -> slot rs ready
        const float4 v = ring_warp[rs * 32 + lane];
        const int nj = j + AHEAD;
        if (nj < count) {
            int r;
            if (nj < 32) r = __shfl_sync(FULL_MASK, myidx, nj) + base;
            else         r = (int)indices[start + nj] + base;
            cp_async16(smem_warp_base + (uint32_t)((ws * 32 + lane) << 4),
                       (const void*)&w4[(long long)r * 32 + lane]);
        }
        cp_commit();
        acc.x += v.x; acc.y += v.y; acc.z += v.z; acc.w += v.w;
        rs = (rs + 1 == SLOTS) ? 0 : rs + 1;
        ws = (ws + 1 == SLOTS) ? 0 : ws + 1;
    }
    cp_wait<0>();   // drain trailing empty groups

    ((float4*)out)[((long long)b * n_tables + table) * 32 + lane] = acc;
}

__global__ __launch_bounds__(256, 8)
void tbe_fwd_d128_kernel(const void* __restrict__ indices_raw,
                         const void* __restrict__ offsets_raw,
                         const float* __restrict__ weights,
                         const void* __restrict__ hash_cumsum_raw,
                         float* __restrict__ out,
                         int num_bags, int batch, int n_tables) {
    __shared__ __align__(16) float4 ring[8 * SLOTS * 32];   // 24 KB

    const int warp = threadIdx.x >> 5;
    const int lane = threadIdx.x & 31;
    const int bag  = blockIdx.x * 8 + warp;
    if (bag >= num_bags) return;

    float4* ring_warp = &ring[warp * SLOTS * 32];
    const uint32_t smem_warp_base =
        (uint32_t)__cvta_generic_to_shared(ring_warp);

    // dtype sniff: offsets strictly increasing from 0 (uniform branch)
    const bool is64 = (((const int*)offsets_raw)[1] == 0);

    if (is64) {
        bag_pipe<long long>((const long long*)indices_raw,
                            (const long long*)offsets_raw,
                            weights,
                            (const long long*)hash_cumsum_raw,
                            out, smem_warp_base, ring_warp,
                            bag, batch, n_tables, lane);
    } else {
        bag_pipe<int>((const int*)indices_raw,
                      (const int*)offsets_raw,
                      weights,
                      (const int*)hash_cumsum_raw,
                      out, smem_warp_base, ring_warp,
                      bag, batch, n_tables, lane);
    }
}

// Generic fallback for D != 128: one thread per output element (int32 idx).
template <typename IdxT>
__global__ void tbe_fwd_generic_kernel(const IdxT* __restrict__ indices,
                                       const IdxT* __restrict__ offsets,
                                       const float* __restrict__ weights,
                                       const IdxT* __restrict__ hash_cumsum,
                                       float* __restrict__ out,
                                       int num_bags, int batch, int n_tables,
                                       int D) {
    long long gid = (long long)blockIdx.x * blockDim.x + threadIdx.x;
    long long total = (long long)num_bags * D;
    if (gid >= total) return;
    int bag = (int)(gid / D);
    int d   = (int)(gid - (long long)bag * D);
    int table = bag / batch;
    int b     = bag - table * batch;
    long long start = (long long)offsets[bag];
    long long end   = (long long)offsets[bag + 1];
    long long base  = (long long)hash_cumsum[table];
    float acc = 0.f;
    for (long long j = start; j < end; ++j) {
        long long row = (long long)indices[j] + base;
        acc += weights[row * D + d];
    }
    out[((long long)b * n_tables + table) * D + d] = acc;
}

extern "C" void kernel_launch(void* const* d_in, const int* in_sizes, int n_in,
                              void* d_out, int out_size) {
    const void*  indices     = d_in[0];
    const void*  offsets     = d_in[1];
    const float* weights     = (const float*)d_in[2];
    const void*  hash_cumsum = d_in[3];
    float* out = (float*)d_out;

    const int num_bags = in_sizes[1] - 1;        // T*B
    const int n_tables = in_sizes[3] - 1;        // T
    const int batch    = num_bags / n_tables;    // B
    const int D        = out_size / num_bags;    // 128 expected

    if (D == 128) {
        const int warps_per_block = 8;
        const int grid = (num_bags + warps_per_block - 1) / warps_per_block;
        tbe_fwd_d128_kernel<<<grid, 256>>>(indices, offsets, weights,
                                           hash_cumsum, out,
                                           num_bags, batch, n_tables);
    } else {
        long long total = (long long)num_bags * D;
        int grid = (int)((total + 255) / 256);
        tbe_fwd_generic_kernel<int><<<grid, 256>>>(
            (const int*)indices, (const int*)offsets, weights,
            (const int*)hash_cumsum, out, num_bags, batch, n_tables, D);
    }
}